// round 4
// baseline (speedup 1.0000x reference)
#include <cuda_runtime.h>
#include <cuda_bf16.h>
#include <cstdint>

// ============================================================================
// GroupWiseLinearProjector via mma.sync bf16x3-split GEMM (compute_103-safe)
//   x  : [16, 512, 64, 64] f32
//   Wg : [16, 512, 512]    f32  (phase p = (h%4)*4 + (w%4))
//   out[b,o,h,w] = sum_c x[b,c,h,w] * Wg[p,o,c]
// Per (b, phase): D[512 o, 256 px] = W[512,512] * X[256 px, 512]^T
// fp32 = bf16_hi + bf16_lo;  D = Wh*Xh + Wh*Xl + Wl*Xh  (fp32 accum)
// R4: fused epilogue (no g_tmp/unshuffle), 3-stage cp.async pipeline,
//     q-fastest grid order for L2 store-sector merging.
// ============================================================================

#define B_   16
#define CIN  512
#define COUT 512
#define NPX  256
#define KC   64          // K chunk (64 bf16 = 128B row, SW128 swizzle)
#define NSTAGE 8         // 512 / 64

// ---------------- scratch (device globals; no allocation) ----------------
__device__ __align__(256) unsigned short g_Xh[B_ * 16 * NPX * CIN];   // 64MB
__device__ __align__(256) unsigned short g_Xl[B_ * 16 * NPX * CIN];   // 64MB
__device__ __align__(256) unsigned short g_Wh[16 * COUT * CIN];       // 8MB
__device__ __align__(256) unsigned short g_Wl[16 * COUT * CIN];       // 8MB

// ---------------- helpers ----------------
__device__ __forceinline__ uint32_t smem_to_u32(const void* p) {
    uint32_t a;
    asm("{ .reg .u64 t; cvta.to.shared.u64 t, %1; cvt.u32.u64 %0, t; }"
        : "=r"(a) : "l"(p));
    return a;
}
__device__ __forceinline__ void cp_async16(uint32_t dst, const void* src) {
    asm volatile("cp.async.cg.shared.global [%0], [%1], 16;"
                 :: "r"(dst), "l"(src) : "memory");
}
#define CP_COMMIT() asm volatile("cp.async.commit_group;" ::: "memory")
#define CP_WAIT(n)  asm volatile("cp.async.wait_group %0;" :: "n"(n) : "memory")

__device__ __forceinline__ void ldmx4(uint32_t* r, uint32_t addr) {
    asm volatile("ldmatrix.sync.aligned.m8n8.x4.shared.b16 {%0,%1,%2,%3}, [%4];"
                 : "=r"(r[0]), "=r"(r[1]), "=r"(r[2]), "=r"(r[3]) : "r"(addr));
}
__device__ __forceinline__ void mma16816(float* d, const uint32_t* a,
                                         uint32_t b0, uint32_t b1) {
    asm volatile(
        "mma.sync.aligned.m16n8k16.row.col.f32.bf16.bf16.f32 "
        "{%0,%1,%2,%3}, {%4,%5,%6,%7}, {%8,%9}, {%0,%1,%2,%3};"
        : "+f"(d[0]), "+f"(d[1]), "+f"(d[2]), "+f"(d[3])
        : "r"(a[0]), "r"(a[1]), "r"(a[2]), "r"(a[3]), "r"(b0), "r"(b1));
}
#define SWZ(off) ((uint32_t)(off) ^ ((((uint32_t)(off)) >> 3) & 0x70))

// ============================================================================
// Pass 1a: W -> Wh/Wl bf16 (same layout [ph][o][c])
// ============================================================================
__global__ __launch_bounds__(256)
void convert_w_kernel(const float* __restrict__ Wg) {
    size_t gt = (size_t)blockIdx.x * 256 + threadIdx.x;
    const float4* src = reinterpret_cast<const float4*>(Wg) + gt * 2;
    float4 a = src[0], b = src[1];
    float v[8] = {a.x, a.y, a.z, a.w, b.x, b.y, b.z, b.w};
    unsigned short hb[8], lb[8];
#pragma unroll
    for (int i = 0; i < 8; i++) {
        __nv_bfloat16 h = __float2bfloat16(v[i]);
        float hf = __bfloat162float(h);
        __nv_bfloat16 l = __float2bfloat16(v[i] - hf);
        hb[i] = __bfloat16_as_ushort(h);
        lb[i] = __bfloat16_as_ushort(l);
    }
    uint4 uh, ul;
    uh.x = hb[0] | (uint32_t)hb[1] << 16;  uh.y = hb[2] | (uint32_t)hb[3] << 16;
    uh.z = hb[4] | (uint32_t)hb[5] << 16;  uh.w = hb[6] | (uint32_t)hb[7] << 16;
    ul.x = lb[0] | (uint32_t)lb[1] << 16;  ul.y = lb[2] | (uint32_t)lb[3] << 16;
    ul.z = lb[4] | (uint32_t)lb[5] << 16;  ul.w = lb[6] | (uint32_t)lb[7] << 16;
    *reinterpret_cast<uint4*>(g_Wh + gt * 8) = uh;
    *reinterpret_cast<uint4*>(g_Wl + gt * 8) = ul;
}

// ============================================================================
// Pass 1b: x -> Xh/Xl bf16 in [b][phase][px][c] (K-major)
// ============================================================================
__global__ __launch_bounds__(256)
void convert_x_kernel(const float* __restrict__ x) {
    __shared__ float sin[64][68];
    int bid = blockIdx.x;                 // 16 * 64 * 8 = 8192
    int cc = bid & 7;
    int h  = (bid >> 3) & 63;
    int b  = bid >> 9;
    int c0 = cc * 64;
    int t  = threadIdx.x;

    const float* src = x + (((size_t)b * CIN + c0) * 64 + h) * 64;
    {
        int c  = t >> 2;
        int f0 = t & 3;
#pragma unroll
        for (int j = 0; j < 4; j++) {
            float4 v = *reinterpret_cast<const float4*>(src + (size_t)c * 4096 + (f0 + 4 * j) * 4);
            *reinterpret_cast<float4*>(&sin[c][(f0 + 4 * j) * 4]) = v;
        }
    }
    __syncthreads();

    int p   = t >> 2;
    int q   = p >> 4;
    int w4  = p & 15;
    int cc4 = t & 3;
    int r   = h & 3;
    int h4  = h >> 2;

    unsigned short hb[16], lb[16];
#pragma unroll
    for (int i = 0; i < 16; i++) {
        float v = sin[cc4 * 16 + i][q + 4 * w4];
        __nv_bfloat16 hh = __float2bfloat16(v);
        float hf = __bfloat162float(hh);
        __nv_bfloat16 ll = __float2bfloat16(v - hf);
        hb[i] = __bfloat16_as_ushort(hh);
        lb[i] = __bfloat16_as_ushort(ll);
    }

    int phase = r * 4 + q;
    int px    = h4 * 16 + w4;
    size_t off = (((size_t)(b * 16 + phase) * NPX) + px) * CIN + c0 + cc4 * 16;

    uint4 u0, u1;
    u0.x = hb[0] | (uint32_t)hb[1] << 16;   u0.y = hb[2]  | (uint32_t)hb[3] << 16;
    u0.z = hb[4] | (uint32_t)hb[5] << 16;   u0.w = hb[6]  | (uint32_t)hb[7] << 16;
    u1.x = hb[8] | (uint32_t)hb[9] << 16;   u1.y = hb[10] | (uint32_t)hb[11] << 16;
    u1.z = hb[12]| (uint32_t)hb[13] << 16;  u1.w = hb[14] | (uint32_t)hb[15] << 16;
    *reinterpret_cast<uint4*>(g_Xh + off)     = u0;
    *reinterpret_cast<uint4*>(g_Xh + off + 8) = u1;
    u0.x = lb[0] | (uint32_t)lb[1] << 16;   u0.y = lb[2]  | (uint32_t)lb[3] << 16;
    u0.z = lb[4] | (uint32_t)lb[5] << 16;   u0.w = lb[6]  | (uint32_t)lb[7] << 16;
    u1.x = lb[8] | (uint32_t)lb[9] << 16;   u1.y = lb[10] | (uint32_t)lb[11] << 16;
    u1.z = lb[12]| (uint32_t)lb[13] << 16;  u1.w = lb[14] | (uint32_t)lb[15] << 16;
    *reinterpret_cast<uint4*>(g_Xl + off)     = u0;
    *reinterpret_cast<uint4*>(g_Xl + off + 8) = u1;
}

// ============================================================================
// Pass 2: GEMM via mma.sync, CTA = (b, r, otile 128, ptile 128, q)
//   8 warps: mw = wid&3 (32 o-rows), nw = wid>>2 (64 px)
//   3-stage cp.async pipeline (192KB smem), fused direct-write epilogue.
// ============================================================================
#define STAGE_BYTES 65536
#define T_WH 0
#define T_WL 16384
#define T_XH 32768
#define T_XL 49152

__global__ __launch_bounds__(256, 1)
void gwlp_mma_kernel(float* __restrict__ out) {
    extern __shared__ __align__(1024) char sm[];
    const uint32_t smb = smem_to_u32(sm);

    const int t   = threadIdx.x;
    const int wid = t >> 5;
    const int lid = t & 31;
    const int mw  = wid & 3;    // o sub-tile (32 rows)
    const int nw  = wid >> 2;   // px sub-tile (64 rows)

    // q fastest: the 4 q-sibling CTAs write interleaved w-lattices of the
    // same out sectors; adjacent launch -> concurrent -> L2 store merge.
    const int bid   = blockIdx.x;   // 2048
    const int q     = bid & 3;
    const int ptile = (bid >> 2) & 1;
    const int otile = (bid >> 3) & 3;
    const int r     = (bid >> 5) & 3;
    const int b     = bid >> 7;
    const int phase = r * 4 + q;
    const int o0    = otile * 128;
    const int px0   = ptile * 128;

    const unsigned short* whp = g_Wh + ((size_t)phase * COUT + o0) * CIN;
    const unsigned short* wlp = g_Wl + ((size_t)phase * COUT + o0) * CIN;
    const unsigned short* xhp = g_Xh + ((size_t)(b * 16 + phase) * NPX + px0) * CIN;
    const unsigned short* xlp = g_Xl + ((size_t)(b * 16 + phase) * NPX + px0) * CIN;

    // ---- stage loader (cp.async): 16 x 16B granules per thread ----
    auto load_stage = [&](int s, int buf) {
        const uint32_t sb = smb + (uint32_t)buf * STAGE_BYTES;
        const int ce = s * KC;
#pragma unroll
        for (int i = 0; i < 4; i++) {
            int gi  = t + i * 256;
            int row = gi >> 3, g = gi & 7;
            uint32_t d = sb + SWZ(row * 128 + g * 16);
            size_t so = (size_t)row * CIN + ce + g * 8;
            cp_async16(d + T_WH, whp + so);
            cp_async16(d + T_WL, wlp + so);
            cp_async16(d + T_XH, xhp + so);
            cp_async16(d + T_XL, xlp + so);
        }
        CP_COMMIT();
    };

    // ---- per-lane ldmatrix address components ----
    const int lr = lid & 15;
    const int cb = lid >> 4;
    uint32_t a_off[2], a_key[2];
#pragma unroll
    for (int mt = 0; mt < 2; mt++) {
        int row = mw * 32 + mt * 16 + lr;
        a_off[mt] = (uint32_t)row * 128;
        a_key[mt] = (uint32_t)(row & 7) << 4;
    }
    uint32_t b_off[4], b_key[4];
#pragma unroll
    for (int j = 0; j < 4; j++) {
        int row = nw * 64 + j * 16 + lr;
        b_off[j] = (uint32_t)row * 128;
        b_key[j] = (uint32_t)(row & 7) << 4;
    }

    float acc[2][8][4];
#pragma unroll
    for (int mt = 0; mt < 2; mt++)
#pragma unroll
        for (int nt = 0; nt < 8; nt++)
#pragma unroll
            for (int e = 0; e < 4; e++)
                acc[mt][nt][e] = 0.0f;

    // ---- 3-stage pipeline: single __syncthreads per stage ----
    load_stage(0, 0);
    load_stage(1, 1);

#pragma unroll 1
    for (int ck = 0; ck < NSTAGE; ck++) {
        if (ck == NSTAGE - 1) { CP_WAIT(0); } else { CP_WAIT(1); }
        __syncthreads();
        // issue loads for stage ck+2 into buffer (ck+2)%3 = (ck-1)%3:
        // stage ck-1 was computed last iteration; the sync above makes the
        // whole CTA past it, so its buffer is reusable.
        {
            int nb = ck + 2;
            if (nb < NSTAGE) load_stage(nb, nb % 3);
        }

        const uint32_t sb = smb + (uint32_t)(ck % 3) * STAGE_BYTES;
#pragma unroll
        for (int ks = 0; ks < 4; ks++) {
            const uint32_t kc16 = (uint32_t)(ks * 32 + cb * 16);
            uint32_t ah[2][4], al[2][4], bh[4][4], bl[4][4];
#pragma unroll
            for (int mt = 0; mt < 2; mt++) {
                uint32_t ax = a_off[mt] + (kc16 ^ a_key[mt]);
                ldmx4(ah[mt], sb + T_WH + ax);
                ldmx4(al[mt], sb + T_WL + ax);
            }
#pragma unroll
            for (int j = 0; j < 4; j++) {
                uint32_t bx = b_off[j] + (kc16 ^ b_key[j]);
                ldmx4(bh[j], sb + T_XH + bx);
                ldmx4(bl[j], sb + T_XL + bx);
            }
#pragma unroll
            for (int mt = 0; mt < 2; mt++) {
#pragma unroll
                for (int j = 0; j < 4; j++) {
                    mma16816(acc[mt][2 * j], ah[mt], bh[j][0], bh[j][2]);
                    mma16816(acc[mt][2 * j], ah[mt], bl[j][0], bl[j][2]);
                    mma16816(acc[mt][2 * j], al[mt], bh[j][0], bh[j][2]);
                    mma16816(acc[mt][2 * j + 1], ah[mt], bh[j][1], bh[j][3]);
                    mma16816(acc[mt][2 * j + 1], ah[mt], bl[j][1], bl[j][3]);
                    mma16816(acc[mt][2 * j + 1], al[mt], bh[j][1], bh[j][3]);
                }
            }
        }
    }

    // ---- fused epilogue: regs -> smem [o][px] -> out (direct) ----
    __syncthreads();                       // smem buffers free now
    float (*S)[130] = reinterpret_cast<float (*)[130]>(sm);
    {
        const int g  = lid >> 2;
        const int tq = lid & 3;
#pragma unroll
        for (int mt = 0; mt < 2; mt++) {
#pragma unroll
            for (int nt = 0; nt < 8; nt++) {
                int o  = mw * 32 + mt * 16 + g;
                int px = nw * 64 + nt * 8 + tq * 2;
                S[o][px]         = acc[mt][nt][0];
                S[o][px + 1]     = acc[mt][nt][1];
                S[o + 8][px]     = acc[mt][nt][2];
                S[o + 8][px + 1] = acc[mt][nt][3];
            }
        }
    }
    __syncthreads();

    // each thread owns one w4 column; lanes 0..15 -> consecutive w4 so the
    // 16 stores of a warp cover one contiguous 256B span (stride-16B STG.32).
    {
        const int w4   = t & 15;
        const int rid0 = t >> 4;            // 0..15
        float* obase = out + ((size_t)b * COUT + o0) * 4096
                           + (size_t)r * 64 + q + 4 * w4;
#pragma unroll
        for (int i = 0; i < 64; i++) {
            int rid = rid0 + i * 16;        // 0..1023 = (o, h4l)
            int o   = rid >> 3;
            int h4l = rid & 7;
            int h   = 4 * (ptile * 8 + h4l);
            obase[(size_t)o * 4096 + (size_t)h * 64] = S[o][h4l * 16 + w4];
        }
    }
}

// ============================================================================
extern "C" void kernel_launch(void* const* d_in, const int* in_sizes, int n_in,
                              void* d_out, int out_size)
{
    const float* x  = (const float*)d_in[0];   // [16, 512, 64, 64]
    const float* Wg = (const float*)d_in[1];   // [16, 512, 512]
    float* out = (float*)d_out;                // [16, 512, 64, 64]

    cudaFuncSetAttribute(gwlp_mma_kernel,
                         cudaFuncAttributeMaxDynamicSharedMemorySize, 3 * STAGE_BYTES);

    convert_w_kernel<<<2048, 256>>>(Wg);
    convert_x_kernel<<<8192, 256>>>(x);
    gwlp_mma_kernel<<<2048, 256, 3 * STAGE_BYTES>>>(out);
}